// round 4
// baseline (speedup 1.0000x reference)
#include <cuda_runtime.h>
#include <cuda_bf16.h>
#include <cstdint>

#define Nn   50000
#define Ee   800000
#define F_IN 512
#define H1   256
#define H2   32
#define Cc   16

// ---------------- scratch (device globals; no allocations allowed) ----------
static __device__ float g_h1[(size_t)Nn * H1];   // x @ W1
static __device__ float g_x2[(size_t)Nn * H1];   // relu(agg1 + b1)
static __device__ float g_h2[(size_t)Nn * H2];   // x2 @ W2
static __device__ float g_x3[(size_t)Nn * H2];   // relu(agg2 + b2)
static __device__ float g_h3[(size_t)Nn * Cc];   // x3 @ W3
static __device__ float g_dinv[Nn];
static __device__ int   g_deg[Nn];
static __device__ int   g_incl[Nn];
static __device__ int   g_rowstart[Nn];
static __device__ int   g_fill[Nn];
static __device__ int   g_col[Ee];
static __device__ int   g_blocksums[64];
static __device__ int   g_is64;

// packed f32x2 FMA: d = a*b + d elementwise on two packed floats (Blackwell)
__device__ __forceinline__ void ffma2(unsigned long long& d,
                                      unsigned long long a,
                                      unsigned long long b) {
    asm("fma.rn.f32x2 %0, %1, %2, %0;" : "+l"(d) : "l"(a), "l"(b));
}

// ---------------- edge-index dtype detection --------------------------------
// int64 little-endian with values < 2^31  => every odd 32-bit word is 0.
__global__ void k_detect(const unsigned int* __restrict__ w) {
    if (threadIdx.x == 0 && blockIdx.x == 0) {
        int is64 = 1;
        for (int i = 1; i < 512; i += 2) {
            if (w[i] != 0u) { is64 = 0; break; }
        }
        g_is64 = is64;
    }
}

__device__ __forceinline__ int load_idx(const void* __restrict__ ei, long long idx) {
    if (g_is64) return (int)((const long long*)ei)[idx];
    return ((const int*)ei)[idx];
}

// ---------------- CSR build --------------------------------------------------
__global__ void k_zero_deg() {
    int i = blockIdx.x * blockDim.x + threadIdx.x;
    if (i < Nn) g_deg[i] = 0;
}

__global__ void k_count(const void* __restrict__ ei) {
    int e = blockIdx.x * blockDim.x + threadIdx.x;
    if (e < Ee) {
        int d = load_idx(ei, (long long)Ee + e);
        atomicAdd(&g_deg[d], 1);
    }
}

__global__ void k_scan1() {
    __shared__ int s[1024];
    int t = threadIdx.x;
    int i = blockIdx.x * 1024 + t;
    s[t] = (i < Nn) ? g_deg[i] : 0;
    __syncthreads();
    for (int off = 1; off < 1024; off <<= 1) {
        int add = (t >= off) ? s[t - off] : 0;
        __syncthreads();
        s[t] += add;
        __syncthreads();
    }
    if (i < Nn) g_incl[i] = s[t];
    if (t == 1023) g_blocksums[blockIdx.x] = s[1023];
}

__global__ void k_scan2(int nblocks) {
    if (threadIdx.x == 0) {
        int run = 0;
        for (int i = 0; i < nblocks; i++) {
            int v = g_blocksums[i];
            g_blocksums[i] = run;
            run += v;
        }
    }
}

__global__ void k_scan3() {
    int i = blockIdx.x * blockDim.x + threadIdx.x;
    if (i < Nn) {
        int deg = g_deg[i];
        int start = g_incl[i] - deg + g_blocksums[i >> 10];
        g_rowstart[i] = start;
        g_fill[i] = start;
        g_dinv[i] = rsqrtf((float)(deg + 1));   // +1 self loop
    }
}

__global__ void k_scatter(const void* __restrict__ ei) {
    int e = blockIdx.x * blockDim.x + threadIdx.x;
    if (e < Ee) {
        int s = load_idx(ei, e);
        int d = load_idx(ei, (long long)Ee + e);
        int pos = atomicAdd(&g_fill[d], 1);
        g_col[pos] = s;
    }
}

// ---------------- GEMM1: [Nn,512] x [512,256] -> g_h1 (f32x2 packed) --------
// 64x64 tile, 256 threads, 4x4 outputs/thread via 8 FFMA2 per k-step.
// A values are stored DUPLICATED in shared ((a,a) pairs) so one LDS.128 yields
// two broadcast-packed 64-bit operands; B float4 reinterprets as two packs free.
__global__ void k_gemm1(const float* __restrict__ A, const float* __restrict__ B) {
    __shared__ float As2[16][128];   // k x (2*row) duplicated
    __shared__ float Bs[16][64];     // k x col
    int tid = threadIdx.x;
    int tx = tid & 15, ty = tid >> 4;
    int rowBase = blockIdx.y * 64;
    int colBase = blockIdx.x * 64;

    unsigned long long acc[4][2] = {};   // (4 rows) x (4 cols as 2 f32x2)

    int aRow = tid >> 2;
    int aK4 = (tid & 3) * 4;
    int bK = tid >> 4;
    int bC = (tid & 15) * 4;

    for (int k0 = 0; k0 < F_IN; k0 += 16) {
        int gr = rowBase + aRow;
        float4 av = make_float4(0.f, 0.f, 0.f, 0.f);
        if (gr < Nn) av = *(const float4*)(A + (size_t)gr * F_IN + k0 + aK4);
        *(float2*)(&As2[aK4 + 0][2 * aRow]) = make_float2(av.x, av.x);
        *(float2*)(&As2[aK4 + 1][2 * aRow]) = make_float2(av.y, av.y);
        *(float2*)(&As2[aK4 + 2][2 * aRow]) = make_float2(av.z, av.z);
        *(float2*)(&As2[aK4 + 3][2 * aRow]) = make_float2(av.w, av.w);
        *(float4*)(&Bs[bK][bC]) = *(const float4*)(B + (size_t)(k0 + bK) * H1 + colBase + bC);
        __syncthreads();
#pragma unroll
        for (int kk = 0; kk < 16; kk++) {
            const ulonglong2* ap = (const ulonglong2*)(&As2[kk][ty * 8]);
            ulonglong2 a01 = ap[0];            // (a0,a0) (a1,a1)
            ulonglong2 a23 = ap[1];            // (a2,a2) (a3,a3)
            const ulonglong2* bp = (const ulonglong2*)(&Bs[kk][tx * 4]);
            ulonglong2 b = bp[0];              // (b0,b1) (b2,b3)
            ffma2(acc[0][0], a01.x, b.x); ffma2(acc[0][1], a01.x, b.y);
            ffma2(acc[1][0], a01.y, b.x); ffma2(acc[1][1], a01.y, b.y);
            ffma2(acc[2][0], a23.x, b.x); ffma2(acc[2][1], a23.x, b.y);
            ffma2(acc[3][0], a23.y, b.x); ffma2(acc[3][1], a23.y, b.y);
        }
        __syncthreads();
    }
#pragma unroll
    for (int i = 0; i < 4; i++) {
        int r = rowBase + ty * 4 + i;
        if (r < Nn) {
            float2 lo = *(float2*)(&acc[i][0]);
            float2 hi = *(float2*)(&acc[i][1]);
            float4 v = make_float4(lo.x, lo.y, hi.x, hi.y);
            *(float4*)(g_h1 + (size_t)r * H1 + colBase + tx * 4) = v;
        }
    }
}

// ---------------- GEMM2: g_x2 [Nn,256] x W2 [256,32] -> g_h2 ----------------
__global__ void k_gemm2(const float* __restrict__ W) {
    __shared__ float sA[32][64];
    __shared__ float sW[64][32];
    int tid = threadIdx.x;
    int r = tid >> 3;
    int c4 = (tid & 7) * 4;
    int row0 = blockIdx.x * 32;
    float acc[4] = {0.f, 0.f, 0.f, 0.f};

    for (int k0 = 0; k0 < H1; k0 += 64) {
        for (int i = tid; i < 32 * 16; i += 256) {
            int rr = i >> 4;
            int kk4 = (i & 15) * 4;
            int grow = row0 + rr;
            float4 v = make_float4(0.f, 0.f, 0.f, 0.f);
            if (grow < Nn) v = *(const float4*)(g_x2 + (size_t)grow * H1 + k0 + kk4);
            *(float4*)(&sA[rr][kk4]) = v;
        }
        for (int i = tid; i < 512; i += 256) {
            int kk = i >> 3;
            int cc4 = (i & 7) * 4;
            *(float4*)(&sW[kk][cc4]) = *(const float4*)(W + (size_t)(k0 + kk) * H2 + cc4);
        }
        __syncthreads();
#pragma unroll
        for (int kk = 0; kk < 64; kk++) {
            float a = sA[r][kk];
            acc[0] += a * sW[kk][c4 + 0];
            acc[1] += a * sW[kk][c4 + 1];
            acc[2] += a * sW[kk][c4 + 2];
            acc[3] += a * sW[kk][c4 + 3];
        }
        __syncthreads();
    }
    int row = row0 + r;
    if (row < Nn) {
        float4 v = make_float4(acc[0], acc[1], acc[2], acc[3]);
        *(float4*)(g_h2 + (size_t)row * H2 + c4) = v;
    }
}

// ---------------- GEMM3: g_x3 [Nn,32] x W3 [32,16] -> g_h3 ------------------
__global__ void k_gemm3(const float* __restrict__ W) {
    __shared__ float sW[32 * 16];
    int tid = threadIdx.x;
    for (int i = tid; i < 32 * 16; i += 256) sW[i] = W[i];
    __syncthreads();
    int row = blockIdx.x * 256 + tid;
    if (row >= Nn) return;
    float acc[16];
#pragma unroll
    for (int c = 0; c < 16; c++) acc[c] = 0.f;
    const float4* ap = (const float4*)(g_x3 + (size_t)row * H2);
#pragma unroll
    for (int k4 = 0; k4 < 8; k4++) {
        float4 a = ap[k4];
        int k = k4 * 4;
#pragma unroll
        for (int c = 0; c < 16; c++) {
            acc[c] += a.x * sW[(k + 0) * 16 + c];
            acc[c] += a.y * sW[(k + 1) * 16 + c];
            acc[c] += a.z * sW[(k + 2) * 16 + c];
            acc[c] += a.w * sW[(k + 3) * 16 + c];
        }
    }
    float* op = g_h3 + (size_t)row * Cc;
#pragma unroll
    for (int c4 = 0; c4 < 4; c4++) {
        float4 v = make_float4(acc[c4 * 4 + 0], acc[c4 * 4 + 1], acc[c4 * 4 + 2], acc[c4 * 4 + 3]);
        *(float4*)(op + c4 * 4) = v;
    }
}

// ---------------- Aggregation: out[d] = dinv[d]*Sum(dinv[s]*h[s]) + b -------
// Layer 1: h = g_h1 (F=256), out = g_x2, relu. Warp per node, 8 floats/lane.
__global__ void k_agg256(const float* __restrict__ bias) {
    int warp = threadIdx.x >> 5;
    int lane = threadIdx.x & 31;
    int node = blockIdx.x * 8 + warp;
    if (node >= Nn) return;
    float wd = g_dinv[node];
    const float4* hp = (const float4*)(g_h1 + (size_t)node * 256);
    float4 a0 = hp[lane];
    float4 a1 = hp[32 + lane];
    float4 acc0 = make_float4(a0.x * wd, a0.y * wd, a0.z * wd, a0.w * wd);
    float4 acc1 = make_float4(a1.x * wd, a1.y * wd, a1.z * wd, a1.w * wd);
    int beg = g_rowstart[node];
    int cnt = g_deg[node];
    for (int j = 0; j < cnt; j++) {
        int s = g_col[beg + j];
        float w = g_dinv[s];
        const float4* sp = (const float4*)(g_h1 + (size_t)s * 256);
        float4 v0 = sp[lane];
        float4 v1 = sp[32 + lane];
        acc0.x += w * v0.x; acc0.y += w * v0.y; acc0.z += w * v0.z; acc0.w += w * v0.w;
        acc1.x += w * v1.x; acc1.y += w * v1.y; acc1.z += w * v1.z; acc1.w += w * v1.w;
    }
    float4 b0 = ((const float4*)bias)[lane];
    float4 b1 = ((const float4*)bias)[32 + lane];
    float4 r0 = make_float4(fmaxf(acc0.x * wd + b0.x, 0.f), fmaxf(acc0.y * wd + b0.y, 0.f),
                            fmaxf(acc0.z * wd + b0.z, 0.f), fmaxf(acc0.w * wd + b0.w, 0.f));
    float4 r1 = make_float4(fmaxf(acc1.x * wd + b1.x, 0.f), fmaxf(acc1.y * wd + b1.y, 0.f),
                            fmaxf(acc1.z * wd + b1.z, 0.f), fmaxf(acc1.w * wd + b1.w, 0.f));
    float4* op = (float4*)(g_x2 + (size_t)node * 256);
    op[lane] = r0;
    op[32 + lane] = r1;
}

// Layer 2: h = g_h2 (F=32), out = g_x3, relu. Warp per node, 1 float/lane.
__global__ void k_agg32(const float* __restrict__ bias) {
    int warp = threadIdx.x >> 5;
    int lane = threadIdx.x & 31;
    int node = blockIdx.x * 8 + warp;
    if (node >= Nn) return;
    float wd = g_dinv[node];
    float acc = wd * g_h2[(size_t)node * 32 + lane];
    int beg = g_rowstart[node];
    int cnt = g_deg[node];
    for (int j = 0; j < cnt; j++) {
        int s = g_col[beg + j];
        acc += g_dinv[s] * g_h2[(size_t)s * 32 + lane];
    }
    float r = acc * wd + bias[lane];
    g_x3[(size_t)node * 32 + lane] = fmaxf(r, 0.f);
}

// Layer 3: h = g_h3 (F=16), out = d_out, no relu.
__global__ void k_agg16(const float* __restrict__ bias, float* __restrict__ out) {
    int tid = threadIdx.x;
    int local = tid & 15;
    int node = blockIdx.x * 16 + (tid >> 4);
    if (node >= Nn) return;
    float wd = g_dinv[node];
    float acc = wd * g_h3[(size_t)node * 16 + local];
    int beg = g_rowstart[node];
    int cnt = g_deg[node];
    for (int j = 0; j < cnt; j++) {
        int s = g_col[beg + j];
        acc += g_dinv[s] * g_h3[(size_t)s * 16 + local];
    }
    out[(size_t)node * 16 + local] = acc * wd + bias[local];
}

// ---------------- launch -----------------------------------------------------
extern "C" void kernel_launch(void* const* d_in, const int* in_sizes, int n_in,
                              void* d_out, int out_size) {
    const float* x   = (const float*)d_in[0];
    const void*  ei  = (const void*)d_in[1];
    const float* W1  = (const float*)d_in[2];
    const float* b1  = (const float*)d_in[3];
    const float* W2  = (const float*)d_in[4];
    const float* b2  = (const float*)d_in[5];
    const float* W3  = (const float*)d_in[6];
    const float* b3  = (const float*)d_in[7];
    float* out       = (float*)d_out;

    const int scanBlocks = (Nn + 1023) / 1024;   // 49

    // dtype detect + CSR + norm build
    k_detect<<<1, 32>>>((const unsigned int*)ei);
    k_zero_deg<<<(Nn + 255) / 256, 256>>>();
    k_count<<<(Ee + 255) / 256, 256>>>(ei);
    k_scan1<<<scanBlocks, 1024>>>();
    k_scan2<<<1, 32>>>(scanBlocks);
    k_scan3<<<(Nn + 255) / 256, 256>>>();
    k_scatter<<<(Ee + 255) / 256, 256>>>(ei);

    // Layer 1
    {
        dim3 grid(H1 / 64, (Nn + 63) / 64);
        k_gemm1<<<grid, 256>>>(x, W1);
    }
    k_agg256<<<(Nn + 7) / 8, 256>>>(b1);

    // Layer 2
    k_gemm2<<<(Nn + 31) / 32, 256>>>(W2);
    k_agg32<<<(Nn + 7) / 8, 256>>>(b2);

    // Layer 3
    k_gemm3<<<(Nn + 255) / 256, 256>>>(W3);
    k_agg16<<<(Nn + 15) / 16, 256>>>(b3, out);
}

// round 6
// speedup vs baseline: 1.9279x; 1.9279x over previous
#include <cuda_runtime.h>
#include <cuda_bf16.h>
#include <cstdint>

#define Nn   50000
#define Ee   800000
#define F_IN 512
#define H1   256
#define H2   32
#define Cc   16

// ---------------- scratch (device globals; no allocations allowed) ----------
static __device__ float g_h1[(size_t)Nn * H1];
static __device__ float g_x2[(size_t)Nn * H1];
static __device__ float g_h2[(size_t)Nn * H2];
static __device__ float g_x3[(size_t)Nn * H2];
static __device__ float g_h3[(size_t)Nn * Cc];
static __device__ float g_dinv[Nn];
static __device__ int   g_deg[Nn];
static __device__ int   g_incl[Nn];
static __device__ int   g_rowstart[Nn];
static __device__ int   g_fill[Nn];
static __device__ int   g_col[Ee];
static __device__ int   g_blocksums[64];
static __device__ int   g_is64;
// W1^T split-bf16: [256 n][512 k] (K contiguous = mma "col" B layout)
static __device__ __nv_bfloat16 g_Bh[(size_t)H1 * F_IN];
static __device__ __nv_bfloat16 g_Bl[(size_t)H1 * F_IN];

// ---------------- helpers ----------------------------------------------------
__device__ __forceinline__ uint32_t smem_u32(const void* p) {
    uint32_t a;
    asm("{ .reg .u64 t; cvta.to.shared.u64 t, %1; cvt.u32.u64 %0, t; }" : "=r"(a) : "l"(p));
    return a;
}
__device__ __forceinline__ unsigned pack_bf2(float a, float b) {
    __nv_bfloat162 t(__float2bfloat16(a), __float2bfloat16(b));
    return *(unsigned*)&t;
}
__device__ __forceinline__ void ldm_x4(unsigned* r, uint32_t addr) {
    asm volatile("ldmatrix.sync.aligned.m8n8.x4.shared.b16 {%0,%1,%2,%3}, [%4];"
                 : "=r"(r[0]), "=r"(r[1]), "=r"(r[2]), "=r"(r[3]) : "r"(addr));
}
__device__ __forceinline__ void mma_bf16(float* c, const unsigned* a, const unsigned* b) {
    asm volatile(
        "mma.sync.aligned.m16n8k16.row.col.f32.bf16.bf16.f32 "
        "{%0,%1,%2,%3},{%4,%5,%6,%7},{%8,%9},{%0,%1,%2,%3};"
        : "+f"(c[0]), "+f"(c[1]), "+f"(c[2]), "+f"(c[3])
        : "r"(a[0]), "r"(a[1]), "r"(a[2]), "r"(a[3]), "r"(b[0]), "r"(b[1]));
}

// ---------------- edge-index dtype detection --------------------------------
__global__ void k_detect(const unsigned int* __restrict__ w) {
    if (threadIdx.x == 0 && blockIdx.x == 0) {
        int is64 = 1;
        for (int i = 1; i < 512; i += 2) {
            if (w[i] != 0u) { is64 = 0; break; }
        }
        g_is64 = is64;
    }
}
__device__ __forceinline__ int load_idx(const void* __restrict__ ei, long long idx) {
    if (g_is64) return (int)((const long long*)ei)[idx];
    return ((const int*)ei)[idx];
}

// ---------------- CSR build --------------------------------------------------
__global__ void k_zero_deg() {
    int i = blockIdx.x * blockDim.x + threadIdx.x;
    if (i < Nn) g_deg[i] = 0;
}
__global__ void k_count(const void* __restrict__ ei) {
    int e = blockIdx.x * blockDim.x + threadIdx.x;
    if (e < Ee) atomicAdd(&g_deg[load_idx(ei, (long long)Ee + e)], 1);
}
__global__ void k_scan1() {
    __shared__ int s[1024];
    int t = threadIdx.x;
    int i = blockIdx.x * 1024 + t;
    s[t] = (i < Nn) ? g_deg[i] : 0;
    __syncthreads();
    for (int off = 1; off < 1024; off <<= 1) {
        int add = (t >= off) ? s[t - off] : 0;
        __syncthreads();
        s[t] += add;
        __syncthreads();
    }
    if (i < Nn) g_incl[i] = s[t];
    if (t == 1023) g_blocksums[blockIdx.x] = s[1023];
}
__global__ void k_scan2(int nblocks) {
    if (threadIdx.x == 0) {
        int run = 0;
        for (int i = 0; i < nblocks; i++) { int v = g_blocksums[i]; g_blocksums[i] = run; run += v; }
    }
}
__global__ void k_scan3() {
    int i = blockIdx.x * blockDim.x + threadIdx.x;
    if (i < Nn) {
        int deg = g_deg[i];
        int start = g_incl[i] - deg + g_blocksums[i >> 10];
        g_rowstart[i] = start;
        g_fill[i] = start;
        g_dinv[i] = rsqrtf((float)(deg + 1));
    }
}
__global__ void k_scatter(const void* __restrict__ ei) {
    int e = blockIdx.x * blockDim.x + threadIdx.x;
    if (e < Ee) {
        int s = load_idx(ei, e);
        int d = load_idx(ei, (long long)Ee + e);
        int pos = atomicAdd(&g_fill[d], 1);
        g_col[pos] = s;
    }
}

// ---------------- W1 transpose + split-bf16 ----------------------------------
__global__ void k_cvtW(const float* __restrict__ W1) {
    int i = blockIdx.x * blockDim.x + threadIdx.x;
    if (i < F_IN * H1) {
        int k = i >> 8;
        int n = i & 255;
        float v = W1[i];
        __nv_bfloat16 h = __float2bfloat16(v);
        __nv_bfloat16 l = __float2bfloat16(v - __bfloat162float(h));
        g_Bh[(size_t)n * F_IN + k] = h;
        g_Bl[(size_t)n * F_IN + k] = l;
    }
}

// ---------------- GEMM1: mma.sync split-bf16 ---------------------------------
// Block 128x64, 8 warps (4x2), warp 32x32 = 2 m16 x 4 n8 tiles. K chunks of 64.
// Smem layout: [row][seg] 16B segments, phys seg = seg ^ (row&7) (conflict-free
// ldmatrix). A: 128x8 segs, B: 64x8 segs.
__global__ void __launch_bounds__(256) k_gemm1_mma(const float* __restrict__ A) {
    __shared__ uint4 sAh[128 * 8];
    __shared__ uint4 sAl[128 * 8];
    __shared__ uint4 sBh[64 * 8];
    __shared__ uint4 sBl[64 * 8];

    int tid = threadIdx.x;
    int wid = tid >> 5;
    int lane = tid & 31;
    int warp_m = wid & 3;           // 0..3 -> 32-row slice
    int warp_n = wid >> 2;          // 0..1 -> 32-col slice
    int colBase = blockIdx.x * 64;
    int row0 = blockIdx.y * 128;

    float acc[2][4][4];
#pragma unroll
    for (int mt = 0; mt < 2; mt++)
#pragma unroll
        for (int nt = 0; nt < 4; nt++)
#pragma unroll
            for (int q = 0; q < 4; q++) acc[mt][nt][q] = 0.f;

    uint32_t baseAh = smem_u32(sAh), baseAl = smem_u32(sAl);
    uint32_t baseBh = smem_u32(sBh), baseBl = smem_u32(sBl);

    for (int k0 = 0; k0 < F_IN; k0 += 64) {
        // stage A: 128 rows x 8 segs (8 fp32 -> 8 bf16 hi + 8 lo per seg)
        for (int i = tid; i < 1024; i += 256) {
            int r = i >> 3;
            int seg = i & 7;
            int gr = row0 + r;
            if (gr >= Nn) gr = Nn - 1;
            const float4* p = (const float4*)(A + (size_t)gr * F_IN + k0 + seg * 8);
            float4 v0 = p[0], v1 = p[1];
            uint4 hi, lo;
            hi.x = pack_bf2(v0.x, v0.y); hi.y = pack_bf2(v0.z, v0.w);
            hi.z = pack_bf2(v1.x, v1.y); hi.w = pack_bf2(v1.z, v1.w);
            float lx = v0.x - __bfloat162float(__float2bfloat16(v0.x));
            float ly = v0.y - __bfloat162float(__float2bfloat16(v0.y));
            float lz = v0.z - __bfloat162float(__float2bfloat16(v0.z));
            float lw = v0.w - __bfloat162float(__float2bfloat16(v0.w));
            lo.x = pack_bf2(lx, ly); lo.y = pack_bf2(lz, lw);
            lx = v1.x - __bfloat162float(__float2bfloat16(v1.x));
            ly = v1.y - __bfloat162float(__float2bfloat16(v1.y));
            lz = v1.z - __bfloat162float(__float2bfloat16(v1.z));
            lw = v1.w - __bfloat162float(__float2bfloat16(v1.w));
            lo.z = pack_bf2(lx, ly); lo.w = pack_bf2(lz, lw);
            int ps = seg ^ (r & 7);
            sAh[r * 8 + ps] = hi;
            sAl[r * 8 + ps] = lo;
        }
        // stage B: 64 n-rows x 8 segs from precomputed bf16 (16B direct)
        for (int i = tid; i < 512; i += 256) {
            int n = i >> 3;
            int seg = i & 7;
            size_t src = (size_t)(colBase + n) * F_IN + k0 + seg * 8;
            int ps = seg ^ (n & 7);
            sBh[n * 8 + ps] = *(const uint4*)((const char*)g_Bh + src * 2);
            sBl[n * 8 + ps] = *(const uint4*)((const char*)g_Bl + src * 2);
        }
        __syncthreads();

#pragma unroll
        for (int s = 0; s < 4; s++) {           // k16 steps within chunk
            unsigned ah[2][4], al[2][4], bh[8], bl[8];
            // A frags: m-tile mt quadrants (q&1 -> row+8, q>>1 -> k+8)
#pragma unroll
            for (int mt = 0; mt < 2; mt++) {
                int q = lane >> 3;
                int r = warp_m * 32 + mt * 16 + (q & 1) * 8 + (lane & 7);
                int seg = s * 2 + (q >> 1);
                uint32_t off = (uint32_t)(r * 8 + (seg ^ (r & 7))) * 16;
                ldm_x4(ah[mt], baseAh + off);
                ldm_x4(al[mt], baseAl + off);
            }
            // B frags: jpair covers 2 n8-tiles per ldmatrix.x4
#pragma unroll
            for (int jp = 0; jp < 2; jp++) {
                int q = lane >> 3;
                int n = warp_n * 32 + (jp * 2 + (q >> 1)) * 8 + (lane & 7);
                int seg = s * 2 + (q & 1);
                uint32_t off = (uint32_t)(n * 8 + (seg ^ (n & 7))) * 16;
                ldm_x4(&bh[jp * 4], baseBh + off);
                ldm_x4(&bl[jp * 4], baseBl + off);
            }
#pragma unroll
            for (int mt = 0; mt < 2; mt++)
#pragma unroll
                for (int nt = 0; nt < 4; nt++) {
                    mma_bf16(acc[mt][nt], ah[mt], &bh[nt * 2]);
                    mma_bf16(acc[mt][nt], ah[mt], &bl[nt * 2]);
                    mma_bf16(acc[mt][nt], al[mt], &bh[nt * 2]);
                }
        }
        __syncthreads();
    }

    // epilogue: C frag thread map (m16n8): c0,c1 @ (lane/4, 2*(lane%4)); c2,c3 @ +8 rows
#pragma unroll
    for (int mt = 0; mt < 2; mt++)
#pragma unroll
        for (int nt = 0; nt < 4; nt++) {
            int r = row0 + warp_m * 32 + mt * 16 + (lane >> 2);
            int col = colBase + warp_n * 32 + nt * 8 + (lane & 3) * 2;
            if (r < Nn)
                *(float2*)(g_h1 + (size_t)r * H1 + col) =
                    make_float2(acc[mt][nt][0], acc[mt][nt][1]);
            if (r + 8 < Nn)
                *(float2*)(g_h1 + (size_t)(r + 8) * H1 + col) =
                    make_float2(acc[mt][nt][2], acc[mt][nt][3]);
        }
}

// ---------------- GEMM2: g_x2 [Nn,256] x W2 [256,32] -> g_h2 ----------------
__global__ void k_gemm2(const float* __restrict__ W) {
    __shared__ float sA[32][64];
    __shared__ float sW[64][32];
    int tid = threadIdx.x;
    int r = tid >> 3;
    int c4 = (tid & 7) * 4;
    int row0 = blockIdx.x * 32;
    float acc[4] = {0.f, 0.f, 0.f, 0.f};
    for (int k0 = 0; k0 < H1; k0 += 64) {
        for (int i = tid; i < 32 * 16; i += 256) {
            int rr = i >> 4;
            int kk4 = (i & 15) * 4;
            int grow = row0 + rr;
            float4 v = make_float4(0.f, 0.f, 0.f, 0.f);
            if (grow < Nn) v = *(const float4*)(g_x2 + (size_t)grow * H1 + k0 + kk4);
            *(float4*)(&sA[rr][kk4]) = v;
        }
        for (int i = tid; i < 512; i += 256) {
            int kk = i >> 3;
            int cc4 = (i & 7) * 4;
            *(float4*)(&sW[kk][cc4]) = *(const float4*)(W + (size_t)(k0 + kk) * H2 + cc4);
        }
        __syncthreads();
#pragma unroll
        for (int kk = 0; kk < 64; kk++) {
            float a = sA[r][kk];
            acc[0] += a * sW[kk][c4 + 0];
            acc[1] += a * sW[kk][c4 + 1];
            acc[2] += a * sW[kk][c4 + 2];
            acc[3] += a * sW[kk][c4 + 3];
        }
        __syncthreads();
    }
    int row = row0 + r;
    if (row < Nn) {
        float4 v = make_float4(acc[0], acc[1], acc[2], acc[3]);
        *(float4*)(g_h2 + (size_t)row * H2 + c4) = v;
    }
}

// ---------------- GEMM3: g_x3 [Nn,32] x W3 [32,16] -> g_h3 ------------------
__global__ void k_gemm3(const float* __restrict__ W) {
    __shared__ float sW[32 * 16];
    int tid = threadIdx.x;
    for (int i = tid; i < 32 * 16; i += 256) sW[i] = W[i];
    __syncthreads();
    int row = blockIdx.x * 256 + tid;
    if (row >= Nn) return;
    float acc[16];
#pragma unroll
    for (int c = 0; c < 16; c++) acc[c] = 0.f;
    const float4* ap = (const float4*)(g_x3 + (size_t)row * H2);
#pragma unroll
    for (int k4 = 0; k4 < 8; k4++) {
        float4 a = ap[k4];
        int k = k4 * 4;
#pragma unroll
        for (int c = 0; c < 16; c++) {
            acc[c] += a.x * sW[(k + 0) * 16 + c];
            acc[c] += a.y * sW[(k + 1) * 16 + c];
            acc[c] += a.z * sW[(k + 2) * 16 + c];
            acc[c] += a.w * sW[(k + 3) * 16 + c];
        }
    }
    float* op = g_h3 + (size_t)row * Cc;
#pragma unroll
    for (int c4 = 0; c4 < 4; c4++) {
        float4 v = make_float4(acc[c4 * 4 + 0], acc[c4 * 4 + 1], acc[c4 * 4 + 2], acc[c4 * 4 + 3]);
        *(float4*)(op + c4 * 4) = v;
    }
}

// ---------------- Aggregation ------------------------------------------------
__global__ void k_agg256(const float* __restrict__ bias) {
    int warp = threadIdx.x >> 5;
    int lane = threadIdx.x & 31;
    int node = blockIdx.x * 8 + warp;
    if (node >= Nn) return;
    float wd = g_dinv[node];
    const float4* hp = (const float4*)(g_h1 + (size_t)node * 256);
    float4 a0 = hp[lane];
    float4 a1 = hp[32 + lane];
    float4 acc0 = make_float4(a0.x * wd, a0.y * wd, a0.z * wd, a0.w * wd);
    float4 acc1 = make_float4(a1.x * wd, a1.y * wd, a1.z * wd, a1.w * wd);
    int beg = g_rowstart[node];
    int cnt = g_deg[node];
    for (int j = 0; j < cnt; j++) {
        int s = g_col[beg + j];
        float w = g_dinv[s];
        const float4* sp = (const float4*)(g_h1 + (size_t)s * 256);
        float4 v0 = sp[lane];
        float4 v1 = sp[32 + lane];
        acc0.x += w * v0.x; acc0.y += w * v0.y; acc0.z += w * v0.z; acc0.w += w * v0.w;
        acc1.x += w * v1.x; acc1.y += w * v1.y; acc1.z += w * v1.z; acc1.w += w * v1.w;
    }
    float4 b0 = ((const float4*)bias)[lane];
    float4 b1 = ((const float4*)bias)[32 + lane];
    float4 r0 = make_float4(fmaxf(acc0.x * wd + b0.x, 0.f), fmaxf(acc0.y * wd + b0.y, 0.f),
                            fmaxf(acc0.z * wd + b0.z, 0.f), fmaxf(acc0.w * wd + b0.w, 0.f));
    float4 r1 = make_float4(fmaxf(acc1.x * wd + b1.x, 0.f), fmaxf(acc1.y * wd + b1.y, 0.f),
                            fmaxf(acc1.z * wd + b1.z, 0.f), fmaxf(acc1.w * wd + b1.w, 0.f));
    float4* op = (float4*)(g_x2 + (size_t)node * 256);
    op[lane] = r0;
    op[32 + lane] = r1;
}

__global__ void k_agg32(const float* __restrict__ bias) {
    int warp = threadIdx.x >> 5;
    int lane = threadIdx.x & 31;
    int node = blockIdx.x * 8 + warp;
    if (node >= Nn) return;
    float wd = g_dinv[node];
    float acc = wd * g_h2[(size_t)node * 32 + lane];
    int beg = g_rowstart[node];
    int cnt = g_deg[node];
    for (int j = 0; j < cnt; j++) {
        int s = g_col[beg + j];
        acc += g_dinv[s] * g_h2[(size_t)s * 32 + lane];
    }
    float r = acc * wd + bias[lane];
    g_x3[(size_t)node * 32 + lane] = fmaxf(r, 0.f);
}

__global__ void k_agg16(const float* __restrict__ bias, float* __restrict__ out) {
    int tid = threadIdx.x;
    int local = tid & 15;
    int node = blockIdx.x * 16 + (tid >> 4);
    if (node >= Nn) return;
    float wd = g_dinv[node];
    float acc = wd * g_h3[(size_t)node * 16 + local];
    int beg = g_rowstart[node];
    int cnt = g_deg[node];
    for (int j = 0; j < cnt; j++) {
        int s = g_col[beg + j];
        acc += g_dinv[s] * g_h3[(size_t)s * 16 + local];
    }
    out[(size_t)node * 16 + local] = acc * wd + bias[local];
}

// ---------------- launch -----------------------------------------------------
extern "C" void kernel_launch(void* const* d_in, const int* in_sizes, int n_in,
                              void* d_out, int out_size) {
    const float* x   = (const float*)d_in[0];
    const void*  ei  = (const void*)d_in[1];
    const float* W1  = (const float*)d_in[2];
    const float* b1  = (const float*)d_in[3];
    const float* W2  = (const float*)d_in[4];
    const float* b2  = (const float*)d_in[5];
    const float* W3  = (const float*)d_in[6];
    const float* b3  = (const float*)d_in[7];
    float* out       = (float*)d_out;

    const int scanBlocks = (Nn + 1023) / 1024;   // 49

    k_detect<<<1, 32>>>((const unsigned int*)ei);
    k_zero_deg<<<(Nn + 255) / 256, 256>>>();
    k_count<<<(Ee + 255) / 256, 256>>>(ei);
    k_scan1<<<scanBlocks, 1024>>>();
    k_scan2<<<1, 32>>>(scanBlocks);
    k_scan3<<<(Nn + 255) / 256, 256>>>();
    k_scatter<<<(Ee + 255) / 256, 256>>>(ei);

    // Layer 1 (HMMA split-bf16)
    k_cvtW<<<(F_IN * H1 + 255) / 256, 256>>>(W1);
    {
        dim3 grid(H1 / 64, (Nn + 127) / 128);
        k_gemm1_mma<<<grid, 256>>>(x);
    }
    k_agg256<<<(Nn + 7) / 8, 256>>>(b1);

    // Layer 2
    k_gemm2<<<(Nn + 31) / 32, 256>>>(W2);
    k_agg32<<<(Nn + 7) / 8, 256>>>(b2);

    // Layer 3
    k_gemm3<<<(Nn + 255) / 256, 256>>>(W3);
    k_agg16<<<(Nn + 15) / 16, 256>>>(b3, out);
}